// round 15
// baseline (speedup 1.0000x reference)
#include <cuda_runtime.h>
#include <cuda_bf16.h>
#include <math.h>
#include <stdint.h>

#define NF 32
#define Dm 256
#define Hh 128
#define Bb 16
#define Tt 512
#define BT (Bb*Tt)      // 8192 positions
#define MT 128          // positions per CTA in pass1
#define PW 136          // bf16 pitch (elems) of prepped weight / h tiles
#define PWB 272         // bytes

// ---------------- scratch (device globals; no runtime allocation) ----------
__device__ float g_stacked[(size_t)BT*NF*Dm];   // 268 MB pre-LN y (B,T,F,D)
__device__ float g_rs[(size_t)BT*NF];           // per (p,f) 1/std
__device__ float g_mu[(size_t)BT*NF];           // per (p,f) mean
__device__ float g_pooledA[Bb*NF*Dm];           // sum_t rs_t * y[t,d]
__device__ float g_pooledB[Bb*NF];              // sum_t rs_t * mu_t
__device__ float g_weights[Bb*NF];
__device__ float g_h1[Bb*Dm];                   // split-K partials of fp@W1
__device__ float g_sk[Bb*NF];                   // split-K partials of fp@Ws
// prepped weights: 128 parts (f*4 + t*2 + hilo), each [256 d][136 k] bf16
__device__ uint4 g_wprep4[128 * 4352];          // 8.9 MB

// ---------------- helpers --------------------------------------------------
__device__ __forceinline__ uint32_t smem_u32(const void* p){
    uint32_t a;
    asm("{ .reg .u64 t; cvta.to.shared.u64 t, %1; cvt.u32.u64 %0, t; }" : "=r"(a) : "l"(p));
    return a;
}
__device__ __forceinline__ void ldsm_x4(uint32_t (&r)[4], uint32_t a){
    asm volatile("ldmatrix.sync.aligned.m8n8.x4.shared.b16 {%0,%1,%2,%3}, [%4];"
        : "=r"(r[0]),"=r"(r[1]),"=r"(r[2]),"=r"(r[3]) : "r"(a));
}
__device__ __forceinline__ void mma16816(float* c, const uint32_t (&a)[4],
                                         uint32_t b0, uint32_t b1){
    asm volatile("mma.sync.aligned.m16n8k16.row.col.f32.bf16.bf16.f32 "
        "{%0,%1,%2,%3}, {%4,%5,%6,%7}, {%8,%9}, {%0,%1,%2,%3};"
        : "+f"(c[0]),"+f"(c[1]),"+f"(c[2]),"+f"(c[3])
        : "r"(a[0]),"r"(a[1]),"r"(a[2]),"r"(a[3]), "r"(b0),"r"(b1));
}
#define CP16(d,s)    asm volatile("cp.async.cg.shared.global [%0], [%1], 16;" :: "r"(d), "l"(s) : "memory")
#define CP_COMMIT()  asm volatile("cp.async.commit_group;" ::: "memory")
#define CP_WAIT(n)   asm volatile("cp.async.wait_group %0;" :: "n"(n) : "memory")

__device__ __forceinline__ float eluf(float z){ return z > 0.f ? z : expm1f(z); }
__device__ __forceinline__ float sigf(float z){ return __fdividef(1.f, 1.f + __expf(-z)); }

// ---------------------------------------------------------------------------
// K1: prep (w2/wg -> bf16 hi/lo transposed pitch-136 images) + zero scratch.
// grid = 514: blocks 0..511 prep (f,t,p,dc), 512..513 zero.
// ---------------------------------------------------------------------------
__global__ void __launch_bounds__(256,1) vsn_prep(const float* __restrict__ w2,
                                                  const float* __restrict__ wg)
{
    __shared__ float ts[128][65];
    const int bid = blockIdx.x;
    const int tid = threadIdx.x;

    if (bid >= 512){
        int z = bid - 512;
        for (int i = z*65536 + tid; i < z*65536 + 65536; i += 256) g_pooledA[i] = 0.f;
        if (z == 0){
            for (int i = tid; i < Bb*Dm; i += 256) g_h1[i] = 0.f;
            for (int i = tid; i < Bb*NF; i += 256){ g_sk[i] = 0.f; g_pooledB[i] = 0.f; }
        }
        return;
    }

    const int f = bid >> 4, t = (bid >> 3) & 1, p = (bid >> 2) & 1, dc = bid & 3;
    const int part = (f*2 + t)*2 + p;
    const float* W = (t ? wg : w2) + (size_t)f*Hh*Dm;                    // [k][d]
    __nv_bfloat16* dst = (__nv_bfloat16*)(g_wprep4 + (size_t)part*4352); // [d][k pitch 136]

    #pragma unroll
    for (int i = 0; i < 32; i++){
        int e = tid + i*256;
        int d = e & 63, k = e >> 6;
        ts[k][d] = W[(size_t)k*Dm + dc*64 + d];
    }
    __syncthreads();
    #pragma unroll
    for (int i = 0; i < 4; i++){
        int g = tid + i*256;
        int d = g >> 4, kg = g & 15;
        union { __nv_bfloat16 h[8]; uint4 v; } o;
        #pragma unroll
        for (int j = 0; j < 8; j++){
            float v = ts[kg*8 + j][d];
            __nv_bfloat16 hi = __float2bfloat16(v);
            o.h[j] = p ? __float2bfloat16(v - __bfloat162float(hi)) : hi;
        }
        *(uint4*)(dst + (size_t)(dc*64 + d)*PW + kg*8) = o.v;
    }
}

// ---------------------------------------------------------------------------
// K2 / Pass 1: HMMA bf16, MT=128, DC=32, 2 CTAs/SM.
// proj 3-term split, gate 2-term. R15: B ldsm fused via per-lane-group x4
// addressing (proj hi+lo in one x4; gate nt0+nt1 in one x4): 10 -> 7 ldsm/kk.
// grid = (NF, 64), 256 threads, 110080 B dyn smem.
// ---------------------------------------------------------------------------
#define OFF_HHI 0
#define OFF_HLO 34816
#define OFF_WT  69632           // 3 parts x 8704 = 26112 staged (w2hi,w2lo,wghi)
#define OFF_B2  104448
#define OFF_BG  105472
#define OFF_WS  106496
#define OFF_BS  107520
#define OFF_W1  108544
#define OFF_B1  109056
#define OFF_X   109568
#define SMEM1_BYTES 110080
// post-loop overlays in WT: sred [2][128]f32 @+0, ssq @+1024, rs_s[128] @+2048,
// pbm[128] @+2560

extern __shared__ char sm1[];

__global__ void __launch_bounds__(256,2) vsn_pass1(
    const float* __restrict__ x,  const float* __restrict__ w1, const float* __restrict__ b1,
    const float* __restrict__ b2, const float* __restrict__ bg,
    const float* __restrict__ ws, const float* __restrict__ bs)
{
    const int f     = blockIdx.x;
    const int pbase = blockIdx.y * MT;
    const int b     = pbase >> 9;
    const int tid   = threadIdx.x;
    const int lane  = tid & 31;
    const int wid   = tid >> 5;
    const int q     = wid & 1;      // 16-col group within 32-d chunk
    const int rg    = wid >> 1;     // 32-row group

    char* HHI = sm1 + OFF_HHI;      // [128][272 B] bf16 hi
    char* HLO = sm1 + OFF_HLO;
    float* b2_s = (float*)(sm1 + OFF_B2);
    float* bg_s = (float*)(sm1 + OFF_BG);
    float* ws_s = (float*)(sm1 + OFF_WS);
    float* bs_s = (float*)(sm1 + OFF_BS);
    float* w1_s = (float*)(sm1 + OFF_W1);
    float* b1_s = (float*)(sm1 + OFF_B1);
    float* x_s  = (float*)(sm1 + OFF_X);

    const uint32_t sb  = smem_u32(sm1);
    const uint32_t aHI = sb + OFF_HHI, aLO = sb + OFF_HLO, wtb = sb + OFF_WT;
    const char* wsrc = (const char*)g_wprep4 + (size_t)f*4*69632;

    // stage parts: 0 = w2_hi, 1 = w2_lo, 2 = wg_hi
    auto stage = [&](int c){
        const char* srcc = wsrc + (size_t)c*8704;
        #pragma unroll
        for (int p4 = 0; p4 < 3; p4++){
            const char* src = srcc + (size_t)p4*69632;
            const uint32_t dst = wtb + p4*8704;
            CP16(dst + tid*16,       src + (size_t)tid*16);
            CP16(dst + (256+tid)*16, src + (size_t)(256+tid)*16);
            if (tid < 32) CP16(dst + (512+tid)*16, src + (size_t)(512+tid)*16);
        }
    };

    stage(0); CP_COMMIT();

    // ---- stage params ----
    b2_s[tid] = b2[f*Dm + tid];
    bg_s[tid] = bg[f*Dm + tid];
    ws_s[tid] = ws[f*Dm + tid];
    bs_s[tid] = bs[f*Dm + tid];
    if (tid < 128){ w1_s[tid] = w1[f*Hh + tid]; b1_s[tid] = b1[f*Hh + tid]; }
    if (tid < 128) x_s[tid] = x[(size_t)(pbase + tid)*NF + f];
    __syncthreads();

    // ---- h split into bf16 hi/lo rows (row r = tid>>1, k-half (tid&1)*64) ----
    {
        const int r = tid >> 1, k0 = (tid & 1)*64;
        const float x_r = x_s[r];
        #pragma unroll
        for (int j = 0; j < 64; j += 2){
            float v0 = eluf(fmaf(x_r, w1_s[k0+j],   b1_s[k0+j]));
            float v1 = eluf(fmaf(x_r, w1_s[k0+j+1], b1_s[k0+j+1]));
            union { __nv_bfloat16 h[2]; uint32_t u; } hi, lo;
            hi.h[0] = __float2bfloat16(v0);
            hi.h[1] = __float2bfloat16(v1);
            lo.h[0] = __float2bfloat16(v0 - __bfloat162float(hi.h[0]));
            lo.h[1] = __float2bfloat16(v1 - __bfloat162float(hi.h[1]));
            *(uint32_t*)(HHI + r*PWB + (k0+j)*2) = hi.u;
            *(uint32_t*)(HLO + r*PWB + (k0+j)*2) = lo.u;
        }
    }

    const uint32_t a_off = (uint32_t)(((lane & 7) + 8*((lane>>3)&1)) * PWB + ((lane>>4)&1)*16);
    // proj fused hi+lo x4: lanes 0-15 -> hi buf (part 0), lanes 16-31 -> lo buf (part 1)
    const uint32_t bp_off = (uint32_t)((q*16 + (lane & 7))*PWB + ((lane>>3)&1)*16
                                       + ((lane>>4)&1)*8704);
    // gate fused nt0+nt1 x4 (part 2): lanes 0-15 -> nt0 rows, lanes 16-31 -> nt1 rows
    const uint32_t bg_off = (uint32_t)(17408 + (q*16 + (lane & 7))*PWB + ((lane>>3)&1)*16
                                       + ((lane>>4)&1)*(8*PWB));

    float srow[4], ssqrow[4];
    #pragma unroll
    for (int i = 0; i < 4; i++){ srow[i] = 0.f; ssqrow[i] = 0.f; }

    for (int c = 0; c < 8; c++){
        CP_WAIT(0);
        __syncthreads();   // chunk c resident; also orders h/param writes on c=0

        float accp[2][2][4], accg[2][2][4];
        #pragma unroll
        for (int i = 0; i < 2; i++)
            #pragma unroll
            for (int j = 0; j < 2; j++)
                #pragma unroll
                for (int k2 = 0; k2 < 4; k2++){ accp[i][j][k2] = 0.f; accg[i][j][k2] = 0.f; }

        #pragma unroll 2
        for (int kk = 0; kk < 8; kk++){
            // Bp[nt] = {hi_k0, hi_k1, lo_k0, lo_k1}; Bg = {nt0_k0, nt0_k1, nt1_k0, nt1_k1}
            uint32_t Bp[2][4], Bg[4];
            ldsm_x4(Bp[0], wtb + bp_off + kk*32);
            ldsm_x4(Bp[1], wtb + bp_off + (uint32_t)(8*PWB) + kk*32);
            ldsm_x4(Bg,    wtb + bg_off + kk*32);
            #pragma unroll
            for (int mt = 0; mt < 2; mt++){
                uint32_t Ah[4], Al[4];
                const uint32_t aa = (uint32_t)((rg*32 + mt*16)*PWB) + a_off + kk*32;
                ldsm_x4(Ah, aHI + aa);
                ldsm_x4(Al, aLO + aa);
                #pragma unroll
                for (int nt = 0; nt < 2; nt++){
                    mma16816(accp[mt][nt], Ah, Bp[nt][0], Bp[nt][1]);   // proj hi*hi
                    mma16816(accp[mt][nt], Ah, Bp[nt][2], Bp[nt][3]);   // proj hi*lo
                    mma16816(accp[mt][nt], Al, Bp[nt][0], Bp[nt][1]);   // proj lo*hi
                    mma16816(accg[mt][nt], Ah, Bg[nt*2],  Bg[nt*2+1]);  // gate hi*hi
                    mma16816(accg[mt][nt], Al, Bg[nt*2],  Bg[nt*2+1]);  // gate lo*hi
                }
            }
        }
        __syncthreads();   // all warps done reading WT

        if (c + 1 < 8){ stage(c + 1); CP_COMMIT(); }   // overlap with epilogue

        // ---- epilogue: y pre-LN -> gmem, running stats ----
        #pragma unroll
        for (int mt = 0; mt < 2; mt++)
            #pragma unroll
            for (int hf = 0; hf < 2; hf++){
                const int m = rg*32 + mt*16 + (lane>>2) + 8*hf;
                const float xm = x_s[m];
                float* yrow = g_stacked + ((size_t)(pbase + m)*NF + f)*Dm;
                float sacc = 0.f, qacc = 0.f;
                #pragma unroll
                for (int nt = 0; nt < 2; nt++){
                    const int dg = c*32 + q*16 + nt*8 + (lane & 3)*2;
                    float p0 = accp[mt][nt][hf*2+0] + b2_s[dg];
                    float p1 = accp[mt][nt][hf*2+1] + b2_s[dg+1];
                    float g0 = sigf(accg[mt][nt][hf*2+0] + bg_s[dg]);
                    float g1 = sigf(accg[mt][nt][hf*2+1] + bg_s[dg+1]);
                    float y0 = fmaf(xm, ws_s[dg],   bs_s[dg])   + g0*p0;
                    float y1 = fmaf(xm, ws_s[dg+1], bs_s[dg+1]) + g1*p1;
                    float2 yy; yy.x = y0; yy.y = y1;
                    *(float2*)(yrow + dg) = yy;
                    sacc += y0 + y1;
                    qacc = fmaf(y0, y0, fmaf(y1, y1, qacc));
                }
                srow[mt*2 + hf] += sacc;
                ssqrow[mt*2 + hf] += qacc;
            }
    }

    // ---- LN stats -> g_rs / g_mu ----
    __syncthreads();
    float* sred   = (float*)(sm1 + OFF_WT);         // [2 q][128 m]
    float* ssqred = sred + 256;
    float* rs_s   = (float*)(sm1 + OFF_WT + 2048);  // [128]
    float* pbm    = (float*)(sm1 + OFF_WT + 2560);  // [128]
    #pragma unroll
    for (int i = 0; i < 4; i++){
        float v = srow[i], w2v = ssqrow[i];
        v += __shfl_xor_sync(0xffffffffu, v, 1);  w2v += __shfl_xor_sync(0xffffffffu, w2v, 1);
        v += __shfl_xor_sync(0xffffffffu, v, 2);  w2v += __shfl_xor_sync(0xffffffffu, w2v, 2);
        if ((lane & 3) == 0){
            const int m = rg*32 + (i>>1)*16 + (lane>>2) + 8*(i & 1);
            sred[q*128 + m]   = v;
            ssqred[q*128 + m] = w2v;
        }
    }
    __syncthreads();
    if (tid < 128){
        float s  = sred[tid] + sred[128+tid];
        float sq = ssqred[tid] + ssqred[128+tid];
        float mu = s * (1.f/256.f);
        float var = sq * (1.f/256.f) - mu*mu;
        float rs = rsqrtf(var + 1e-5f);
        g_rs[(size_t)(pbase + tid)*NF + f] = rs;
        g_mu[(size_t)(pbase + tid)*NF + f] = mu;
        rs_s[tid] = rs;
        pbm[tid]  = rs * mu;
    }
    __syncthreads();

    // ---- fused pool: L2-hot readback of this CTA's y, 1 atomic per d ----
    {
        const float* yp = g_stacked + ((size_t)pbase*NF + f)*Dm + tid;
        float acc = 0.f;
        #pragma unroll 8
        for (int m = 0; m < 128; m++)
            acc = fmaf(rs_s[m], yp[(size_t)m*NF*Dm], acc);
        atomicAdd(&g_pooledA[((size_t)b*NF + f)*Dm + tid], acc);
    }
    if (tid < 32){
        float v = pbm[tid] + pbm[tid+32] + pbm[tid+64] + pbm[tid+96];
        v += __shfl_xor_sync(0xffffffffu, v, 1);
        v += __shfl_xor_sync(0xffffffffu, v, 2);
        v += __shfl_xor_sync(0xffffffffu, v, 4);
        v += __shfl_xor_sync(0xffffffffu, v, 8);
        v += __shfl_xor_sync(0xffffffffu, v, 16);
        if (tid == 0) atomicAdd(&g_pooledB[b*NF + f], v);
    }
}

// ---------------------------------------------------------------------------
// K3 / Pass 2a: weight GRN split-K partials. grid = 256 (f*8 + slice), 256 thr.
// ---------------------------------------------------------------------------
__global__ void __launch_bounds__(256,1) vsn_pass2a(
    const float* __restrict__ lng,const float* __restrict__ lnb,
    const float* __restrict__ W1, const float* __restrict__ Ws)
{
    __shared__ float fp_s[32][16];
    __shared__ float pb_s[16];

    const int f = blockIdx.x >> 3, slice = blockIdx.x & 7;
    const int j0 = slice * 32;
    const int tid = threadIdx.x;
    const float invT = 1.f/(float)Tt;

    if (tid < 16) pb_s[tid] = g_pooledB[tid*NF + f];
    __syncthreads();

    {
        const int j = tid & 31, b8 = tid >> 5;
        const float lg = lng[f*Dm + j0 + j], lb = lnb[f*Dm + j0 + j];
        #pragma unroll
        for (int bb = 0; bb < 2; bb++){
            int b = b8*2 + bb;
            float pa = g_pooledA[((size_t)b*NF + f)*Dm + j0 + j];
            fp_s[j][b] = fmaf(lg*(pa - pb_s[b]), invT, lb);
        }
    }
    __syncthreads();

    {
        float acc[16];
        #pragma unroll
        for (int b = 0; b < 16; b++) acc[b] = 0.f;
        const float* w1p = W1 + (size_t)(f*256 + j0)*Dm + tid;
        #pragma unroll 4
        for (int j = 0; j < 32; j++){
            float w = w1p[(size_t)j*Dm];
            const float4* fv = (const float4*)fp_s[j];
            float4 f0 = fv[0], f1 = fv[1], f2 = fv[2], f3 = fv[3];
            acc[0]  = fmaf(f0.x, w, acc[0]);  acc[1]  = fmaf(f0.y, w, acc[1]);
            acc[2]  = fmaf(f0.z, w, acc[2]);  acc[3]  = fmaf(f0.w, w, acc[3]);
            acc[4]  = fmaf(f1.x, w, acc[4]);  acc[5]  = fmaf(f1.y, w, acc[5]);
            acc[6]  = fmaf(f1.z, w, acc[6]);  acc[7]  = fmaf(f1.w, w, acc[7]);
            acc[8]  = fmaf(f2.x, w, acc[8]);  acc[9]  = fmaf(f2.y, w, acc[9]);
            acc[10] = fmaf(f2.z, w, acc[10]); acc[11] = fmaf(f2.w, w, acc[11]);
            acc[12] = fmaf(f3.x, w, acc[12]); acc[13] = fmaf(f3.y, w, acc[13]);
            acc[14] = fmaf(f3.z, w, acc[14]); acc[15] = fmaf(f3.w, w, acc[15]);
        }
        #pragma unroll
        for (int b = 0; b < 16; b++)
            atomicAdd(&g_h1[b*Dm + tid], acc[b]);
    }

    {
        const int k = tid & 31, bg2 = tid >> 5;
        float a0 = 0.f, a1 = 0.f;
        const float* wsp = Ws + (size_t)(f*256 + j0)*NF + k;
        #pragma unroll 4
        for (int j = 0; j < 32; j++){
            float w = wsp[(size_t)j*NF];
            a0 = fmaf(fp_s[j][bg2],   w, a0);
            a1 = fmaf(fp_s[j][bg2+8], w, a1);
        }
        atomicAdd(&g_sk[bg2*NF + k], a0);
        atomicAdd(&g_sk[(bg2+8)*NF + k], a1);
    }
}

// ---------------------------------------------------------------------------
// K4 / Pass 2b: finalize weight GRN per batch. grid = 16, 256 threads.
// ---------------------------------------------------------------------------
__global__ void __launch_bounds__(256,1) vsn_pass2b(
    const float* __restrict__ B1,
    const float* __restrict__ W2, const float* __restrict__ B2,
    const float* __restrict__ Wg, const float* __restrict__ Bg,
    const float* __restrict__ Bs,
    const float* __restrict__ LNg,const float* __restrict__ LNb,
    float* wout)
{
    __shared__ float hw_s[Dm];
    __shared__ float part2[8][NF], part3[8][NF];
    const int b = blockIdx.x, tid = threadIdx.x;

    hw_s[tid] = eluf(g_h1[b*Dm + tid] + B1[tid]);
    __syncthreads();
    {
        const int k = tid & 31, pt = tid >> 5;
        float a2 = 0.f, a3 = 0.f;
        const int d0 = pt*32;
        #pragma unroll
        for (int d = d0; d < d0 + 32; d++){
            float h = hw_s[d];
            a2 = fmaf(h, W2[d*NF + k], a2);
            a3 = fmaf(h, Wg[d*NF + k], a3);
        }
        part2[pt][k] = a2; part3[pt][k] = a3;
    }
    __syncthreads();
    if (tid < 32){
        const int k = tid;
        float pw = B2[k], gw = Bg[k];
        #pragma unroll
        for (int p = 0; p < 8; p++){ pw += part2[p][k]; gw += part3[p][k]; }
        float sk = g_sk[b*NF + k] + Bs[k];
        float v = sk + sigf(gw) * pw;
        float s = v, ssq = v*v;
        #pragma unroll
        for (int o = 16; o > 0; o >>= 1){
            s   += __shfl_xor_sync(0xffffffffu, s, o);
            ssq += __shfl_xor_sync(0xffffffffu, ssq, o);
        }
        float mu = s * (1.f/32.f);
        float var = ssq * (1.f/32.f) - mu*mu;
        float y = fmaf((v - mu) * rsqrtf(var + 1e-5f), LNg[k], LNb[k]);
        float mx = y;
        #pragma unroll
        for (int o = 16; o > 0; o >>= 1) mx = fmaxf(mx, __shfl_xor_sync(0xffffffffu, mx, o));
        float e = expf(y - mx);
        float se = e;
        #pragma unroll
        for (int o = 16; o > 0; o >>= 1) se += __shfl_xor_sync(0xffffffffu, se, o);
        float w = e / se;
        g_weights[b*NF + k] = w;
        if (wout) wout[b*NF + k] = w;
    }
}

// ---------------------------------------------------------------------------
// K5 / Pass 3: fused LN + weighted combine (DRAM-roofline).
// ---------------------------------------------------------------------------
__global__ void __launch_bounds__(256,1) vsn_pass3(
    const float* __restrict__ lng, const float* __restrict__ lnb,
    float* __restrict__ out)
{
    __shared__ float A_s[8][NF], D_s[8][NF], w_s[NF];
    const int p0 = blockIdx.x * 8;
    const int b  = p0 >> 9;
    const int tid = threadIdx.x;

    if (tid < NF) w_s[tid] = g_weights[b*NF + tid];
    __syncthreads();
    {
        const int i = tid >> 5, f2 = tid & 31;
        float rsv = g_rs[(size_t)(p0 + i)*NF + f2];
        float muv = g_mu[(size_t)(p0 + i)*NF + f2];
        float a = w_s[f2] * rsv;
        A_s[i][f2] = a;
        D_s[i][f2] = a * muv;
    }
    float lngr[NF];
    float bias = 0.f;
    #pragma unroll
    for (int f2 = 0; f2 < NF; f2++){
        lngr[f2] = lng[f2*Dm + tid];
        bias = fmaf(lnb[f2*Dm + tid], w_s[f2], bias);
    }
    __syncthreads();

    #pragma unroll
    for (int i = 0; i < 8; i++){
        const float* yrow = g_stacked + ((size_t)(p0 + i)*NF)*Dm + tid;
        float acc = bias;
        #pragma unroll
        for (int f2 = 0; f2 < NF; f2++){
            float y = yrow[(size_t)f2*Dm];
            float t = fmaf(y, A_s[i][f2], -D_s[i][f2]);
            acc = fmaf(lngr[f2], t, acc);
        }
        out[(size_t)(p0 + i)*Dm + tid] = acc;
    }
}

// ---------------------------------------------------------------------------
extern "C" void kernel_launch(void* const* d_in, const int* in_sizes, int n_in,
                              void* d_out, int out_size)
{
    const float* x   = (const float*)d_in[0];
    const float* w1  = (const float*)d_in[1];
    const float* b1  = (const float*)d_in[2];
    const float* w2  = (const float*)d_in[3];
    const float* b2  = (const float*)d_in[4];
    const float* wg  = (const float*)d_in[5];
    const float* bg  = (const float*)d_in[6];
    const float* ws  = (const float*)d_in[7];
    const float* bs  = (const float*)d_in[8];
    const float* lng = (const float*)d_in[9];
    const float* lnb = (const float*)d_in[10];
    const float* W1  = (const float*)d_in[11];
    const float* B1  = (const float*)d_in[12];
    const float* W2  = (const float*)d_in[13];
    const float* B2  = (const float*)d_in[14];
    const float* Wg  = (const float*)d_in[15];
    const float* Bg  = (const float*)d_in[16];
    const float* Ws  = (const float*)d_in[17];
    const float* Bs  = (const float*)d_in[18];
    const float* LNg = (const float*)d_in[19];
    const float* LNb = (const float*)d_in[20];

    cudaFuncSetAttribute(vsn_pass1, cudaFuncAttributeMaxDynamicSharedMemorySize, SMEM1_BYTES);

    float* out = (float*)d_out;
    float* wout = (out_size > BT*Dm) ? out + (size_t)BT*Dm : nullptr;

    vsn_prep<<<514, 256>>>(w2, wg);
    dim3 g1(NF, BT/MT);
    vsn_pass1<<<g1, 256, SMEM1_BYTES>>>(x, w1, b1, b2, bg, ws, bs);
    vsn_pass2a<<<256, 256>>>(lng, lnb, W1, Ws);
    vsn_pass2b<<<16, 256>>>(B1, W2, B2, Wg, Bg, Bs, LNg, LNb, wout);
    vsn_pass3<<<1024, 256>>>(lng, lnb, out);
}

// round 16
// speedup vs baseline: 1.0525x; 1.0525x over previous
#include <cuda_runtime.h>
#include <cuda_bf16.h>
#include <math.h>
#include <stdint.h>

#define NF 32
#define Dm 256
#define Hh 128
#define Bb 16
#define Tt 512
#define BT (Bb*Tt)      // 8192 positions
#define MT 128          // positions per CTA in pass1
#define PW 136          // bf16 pitch (elems) of prepped weight / h tiles
#define PWB 272         // bytes

// ---------------- scratch (device globals; no runtime allocation) ----------
__device__ float g_stacked[(size_t)BT*NF*Dm];   // 268 MB pre-LN y (B,T,F,D)
__device__ float g_rs[(size_t)BT*NF];           // per (p,f) 1/std
__device__ float g_mu[(size_t)BT*NF];           // per (p,f) mean
__device__ float g_pooledA[Bb*NF*Dm];           // sum_t rs_t * y[t,d]
__device__ float g_pooledB[Bb*NF];              // sum_t rs_t * mu_t
__device__ float g_weights[Bb*NF];
__device__ float g_h1[Bb*Dm];                   // split-K partials of fp@W1
__device__ float g_sk[Bb*NF];                   // split-K partials of fp@Ws
// prepped weights: 128 parts (f*4 + t*2 + hilo), each [256 d][136 k] bf16
__device__ uint4 g_wprep4[128 * 4352];          // 8.9 MB

// ---------------- helpers --------------------------------------------------
__device__ __forceinline__ uint32_t smem_u32(const void* p){
    uint32_t a;
    asm("{ .reg .u64 t; cvta.to.shared.u64 t, %1; cvt.u32.u64 %0, t; }" : "=r"(a) : "l"(p));
    return a;
}
__device__ __forceinline__ void ldsm_x4(uint32_t (&r)[4], uint32_t a){
    asm volatile("ldmatrix.sync.aligned.m8n8.x4.shared.b16 {%0,%1,%2,%3}, [%4];"
        : "=r"(r[0]),"=r"(r[1]),"=r"(r[2]),"=r"(r[3]) : "r"(a));
}
__device__ __forceinline__ void ldsm_x2(uint32_t (&r)[2], uint32_t a){
    asm volatile("ldmatrix.sync.aligned.m8n8.x2.shared.b16 {%0,%1}, [%2];"
        : "=r"(r[0]),"=r"(r[1]) : "r"(a));
}
__device__ __forceinline__ void mma16816(float* c, const uint32_t (&a)[4], const uint32_t (&b)[2]){
    asm volatile("mma.sync.aligned.m16n8k16.row.col.f32.bf16.bf16.f32 "
        "{%0,%1,%2,%3}, {%4,%5,%6,%7}, {%8,%9}, {%0,%1,%2,%3};"
        : "+f"(c[0]),"+f"(c[1]),"+f"(c[2]),"+f"(c[3])
        : "r"(a[0]),"r"(a[1]),"r"(a[2]),"r"(a[3]), "r"(b[0]),"r"(b[1]));
}
#define CP16(d,s)    asm volatile("cp.async.cg.shared.global [%0], [%1], 16;" :: "r"(d), "l"(s) : "memory")
#define CP_COMMIT()  asm volatile("cp.async.commit_group;" ::: "memory")
#define CP_WAIT(n)   asm volatile("cp.async.wait_group %0;" :: "n"(n) : "memory")

__device__ __forceinline__ float eluf(float z){ return z > 0.f ? z : expm1f(z); }
__device__ __forceinline__ float sigf(float z){ return __fdividef(1.f, 1.f + __expf(-z)); }

// ---------------------------------------------------------------------------
// K1: prep (w2/wg -> bf16 hi/lo transposed pitch-136 images) + zero scratch.
// grid = 514: blocks 0..511 prep (f,t,p,dc), 512..513 zero.
// ---------------------------------------------------------------------------
__global__ void __launch_bounds__(256,1) vsn_prep(const float* __restrict__ w2,
                                                  const float* __restrict__ wg)
{
    __shared__ float ts[128][65];
    const int bid = blockIdx.x;
    const int tid = threadIdx.x;

    if (bid >= 512){
        int z = bid - 512;
        for (int i = z*65536 + tid; i < z*65536 + 65536; i += 256) g_pooledA[i] = 0.f;
        if (z == 0){
            for (int i = tid; i < Bb*Dm; i += 256) g_h1[i] = 0.f;
            for (int i = tid; i < Bb*NF; i += 256){ g_sk[i] = 0.f; g_pooledB[i] = 0.f; }
        }
        return;
    }

    const int f = bid >> 4, t = (bid >> 3) & 1, p = (bid >> 2) & 1, dc = bid & 3;
    const int part = (f*2 + t)*2 + p;
    const float* W = (t ? wg : w2) + (size_t)f*Hh*Dm;                    // [k][d]
    __nv_bfloat16* dst = (__nv_bfloat16*)(g_wprep4 + (size_t)part*4352); // [d][k pitch 136]

    #pragma unroll
    for (int i = 0; i < 32; i++){
        int e = tid + i*256;
        int d = e & 63, k = e >> 6;
        ts[k][d] = W[(size_t)k*Dm + dc*64 + d];
    }
    __syncthreads();
    #pragma unroll
    for (int i = 0; i < 4; i++){
        int g = tid + i*256;
        int d = g >> 4, kg = g & 15;
        union { __nv_bfloat16 h[8]; uint4 v; } o;
        #pragma unroll
        for (int j = 0; j < 8; j++){
            float v = ts[kg*8 + j][d];
            __nv_bfloat16 hi = __float2bfloat16(v);
            o.h[j] = p ? __float2bfloat16(v - __bfloat162float(hi)) : hi;
        }
        *(uint4*)(dst + (size_t)(dc*64 + d)*PW + kg*8) = o.v;
    }
}

// ---------------------------------------------------------------------------
// K2 / Pass 1: HMMA bf16, MT=128, DC=32, 2 CTAs/SM.
// R16: proj full 3-term split; gate single-term (hi*hi only): 4 MMA/group.
// grid = (NF, 64), 256 threads, 110080 B dyn smem.
// ---------------------------------------------------------------------------
#define OFF_HHI 0
#define OFF_HLO 34816
#define OFF_WT  69632           // 3 parts x 8704 = 26112 staged (w2hi,w2lo,wghi)
#define OFF_B2  104448
#define OFF_BG  105472
#define OFF_WS  106496
#define OFF_BS  107520
#define OFF_W1  108544
#define OFF_B1  109056
#define OFF_X   109568
#define SMEM1_BYTES 110080
// post-loop overlays in WT: sred [2][128]f32 @+0, ssq @+1024, rs_s[128] @+2048,
// pbm[128] @+2560

extern __shared__ char sm1[];

__global__ void __launch_bounds__(256,2) vsn_pass1(
    const float* __restrict__ x,  const float* __restrict__ w1, const float* __restrict__ b1,
    const float* __restrict__ b2, const float* __restrict__ bg,
    const float* __restrict__ ws, const float* __restrict__ bs)
{
    const int f     = blockIdx.x;
    const int pbase = blockIdx.y * MT;
    const int b     = pbase >> 9;
    const int tid   = threadIdx.x;
    const int lane  = tid & 31;
    const int wid   = tid >> 5;
    const int q     = wid & 1;      // 16-col group within 32-d chunk
    const int rg    = wid >> 1;     // 32-row group

    char* HHI = sm1 + OFF_HHI;      // [128][272 B] bf16 hi
    char* HLO = sm1 + OFF_HLO;
    float* b2_s = (float*)(sm1 + OFF_B2);
    float* bg_s = (float*)(sm1 + OFF_BG);
    float* ws_s = (float*)(sm1 + OFF_WS);
    float* bs_s = (float*)(sm1 + OFF_BS);
    float* w1_s = (float*)(sm1 + OFF_W1);
    float* b1_s = (float*)(sm1 + OFF_B1);
    float* x_s  = (float*)(sm1 + OFF_X);

    const uint32_t sb  = smem_u32(sm1);
    const uint32_t aHI = sb + OFF_HHI, aLO = sb + OFF_HLO, wtb = sb + OFF_WT;
    const char* wsrc = (const char*)g_wprep4 + (size_t)f*4*69632;

    // stage parts: 0 = w2_hi, 1 = w2_lo, 2 = wg_hi
    auto stage = [&](int c){
        const char* srcc = wsrc + (size_t)c*8704;
        #pragma unroll
        for (int p4 = 0; p4 < 3; p4++){
            const char* src = srcc + (size_t)p4*69632;
            const uint32_t dst = wtb + p4*8704;
            CP16(dst + tid*16,       src + (size_t)tid*16);
            CP16(dst + (256+tid)*16, src + (size_t)(256+tid)*16);
            if (tid < 32) CP16(dst + (512+tid)*16, src + (size_t)(512+tid)*16);
        }
    };

    stage(0); CP_COMMIT();

    // ---- stage params ----
    b2_s[tid] = b2[f*Dm + tid];
    bg_s[tid] = bg[f*Dm + tid];
    ws_s[tid] = ws[f*Dm + tid];
    bs_s[tid] = bs[f*Dm + tid];
    if (tid < 128){ w1_s[tid] = w1[f*Hh + tid]; b1_s[tid] = b1[f*Hh + tid]; }
    if (tid < 128) x_s[tid] = x[(size_t)(pbase + tid)*NF + f];
    __syncthreads();

    // ---- h split into bf16 hi/lo rows (row r = tid>>1, k-half (tid&1)*64) ----
    {
        const int r = tid >> 1, k0 = (tid & 1)*64;
        const float x_r = x_s[r];
        #pragma unroll
        for (int j = 0; j < 64; j += 2){
            float v0 = eluf(fmaf(x_r, w1_s[k0+j],   b1_s[k0+j]));
            float v1 = eluf(fmaf(x_r, w1_s[k0+j+1], b1_s[k0+j+1]));
            union { __nv_bfloat16 h[2]; uint32_t u; } hi, lo;
            hi.h[0] = __float2bfloat16(v0);
            hi.h[1] = __float2bfloat16(v1);
            lo.h[0] = __float2bfloat16(v0 - __bfloat162float(hi.h[0]));
            lo.h[1] = __float2bfloat16(v1 - __bfloat162float(hi.h[1]));
            *(uint32_t*)(HHI + r*PWB + (k0+j)*2) = hi.u;
            *(uint32_t*)(HLO + r*PWB + (k0+j)*2) = lo.u;
        }
    }

    const uint32_t a_off = (uint32_t)(((lane & 7) + 8*((lane>>3)&1)) * PWB + ((lane>>4)&1)*16);
    const uint32_t b_off = (uint32_t)((q*16 + (lane & 7)) * PWB + ((lane>>3)&1)*16);

    float srow[4], ssqrow[4];
    #pragma unroll
    for (int i = 0; i < 4; i++){ srow[i] = 0.f; ssqrow[i] = 0.f; }

    for (int c = 0; c < 8; c++){
        CP_WAIT(0);
        __syncthreads();   // chunk c resident; also orders h/param writes on c=0

        float accp[2][2][4], accg[2][2][4];
        #pragma unroll
        for (int i = 0; i < 2; i++)
            #pragma unroll
            for (int j = 0; j < 2; j++)
                #pragma unroll
                for (int k2 = 0; k2 < 4; k2++){ accp[i][j][k2] = 0.f; accg[i][j][k2] = 0.f; }

        #pragma unroll 2
        for (int kk = 0; kk < 8; kk++){
            uint32_t Bph[2][2], Bpl[2][2], Bgh[2][2];
            #pragma unroll
            for (int nt = 0; nt < 2; nt++){
                const uint32_t bb = b_off + (uint32_t)(nt*(8*PWB)) + kk*32;
                ldsm_x2(Bph[nt], wtb + bb);
                ldsm_x2(Bpl[nt], wtb + 8704  + bb);
                ldsm_x2(Bgh[nt], wtb + 17408 + bb);
            }
            #pragma unroll
            for (int mt = 0; mt < 2; mt++){
                uint32_t Ah[4], Al[4];
                const uint32_t aa = (uint32_t)((rg*32 + mt*16)*PWB) + a_off + kk*32;
                ldsm_x4(Ah, aHI + aa);
                ldsm_x4(Al, aLO + aa);
                #pragma unroll
                for (int nt = 0; nt < 2; nt++){
                    mma16816(accp[mt][nt], Ah, Bph[nt]);   // proj hi*hi
                    mma16816(accp[mt][nt], Ah, Bpl[nt]);   // proj hi*lo
                    mma16816(accp[mt][nt], Al, Bph[nt]);   // proj lo*hi
                    mma16816(accg[mt][nt], Ah, Bgh[nt]);   // gate hi*hi (only term)
                }
            }
        }
        __syncthreads();   // all warps done reading WT

        if (c + 1 < 8){ stage(c + 1); CP_COMMIT(); }   // overlap with epilogue

        // ---- epilogue: y pre-LN -> gmem, running stats ----
        #pragma unroll
        for (int mt = 0; mt < 2; mt++)
            #pragma unroll
            for (int hf = 0; hf < 2; hf++){
                const int m = rg*32 + mt*16 + (lane>>2) + 8*hf;
                const float xm = x_s[m];
                float* yrow = g_stacked + ((size_t)(pbase + m)*NF + f)*Dm;
                float sacc = 0.f, qacc = 0.f;
                #pragma unroll
                for (int nt = 0; nt < 2; nt++){
                    const int dg = c*32 + q*16 + nt*8 + (lane & 3)*2;
                    float p0 = accp[mt][nt][hf*2+0] + b2_s[dg];
                    float p1 = accp[mt][nt][hf*2+1] + b2_s[dg+1];
                    float g0 = sigf(accg[mt][nt][hf*2+0] + bg_s[dg]);
                    float g1 = sigf(accg[mt][nt][hf*2+1] + bg_s[dg+1]);
                    float y0 = fmaf(xm, ws_s[dg],   bs_s[dg])   + g0*p0;
                    float y1 = fmaf(xm, ws_s[dg+1], bs_s[dg+1]) + g1*p1;
                    float2 yy; yy.x = y0; yy.y = y1;
                    *(float2*)(yrow + dg) = yy;
                    sacc += y0 + y1;
                    qacc = fmaf(y0, y0, fmaf(y1, y1, qacc));
                }
                srow[mt*2 + hf] += sacc;
                ssqrow[mt*2 + hf] += qacc;
            }
    }

    // ---- LN stats -> g_rs / g_mu ----
    __syncthreads();
    float* sred   = (float*)(sm1 + OFF_WT);         // [2 q][128 m]
    float* ssqred = sred + 256;
    float* rs_s   = (float*)(sm1 + OFF_WT + 2048);  // [128]
    float* pbm    = (float*)(sm1 + OFF_WT + 2560);  // [128]
    #pragma unroll
    for (int i = 0; i < 4; i++){
        float v = srow[i], w2v = ssqrow[i];
        v += __shfl_xor_sync(0xffffffffu, v, 1);  w2v += __shfl_xor_sync(0xffffffffu, w2v, 1);
        v += __shfl_xor_sync(0xffffffffu, v, 2);  w2v += __shfl_xor_sync(0xffffffffu, w2v, 2);
        if ((lane & 3) == 0){
            const int m = rg*32 + (i>>1)*16 + (lane>>2) + 8*(i & 1);
            sred[q*128 + m]   = v;
            ssqred[q*128 + m] = w2v;
        }
    }
    __syncthreads();
    if (tid < 128){
        float s  = sred[tid] + sred[128+tid];
        float sq = ssqred[tid] + ssqred[128+tid];
        float mu = s * (1.f/256.f);
        float var = sq * (1.f/256.f) - mu*mu;
        float rs = rsqrtf(var + 1e-5f);
        g_rs[(size_t)(pbase + tid)*NF + f] = rs;
        g_mu[(size_t)(pbase + tid)*NF + f] = mu;
        rs_s[tid] = rs;
        pbm[tid]  = rs * mu;
    }
    __syncthreads();

    // ---- fused pool: L2-hot readback of this CTA's y, 1 atomic per d ----
    {
        const float* yp = g_stacked + ((size_t)pbase*NF + f)*Dm + tid;
        float acc = 0.f;
        #pragma unroll 8
        for (int m = 0; m < 128; m++)
            acc = fmaf(rs_s[m], yp[(size_t)m*NF*Dm], acc);
        atomicAdd(&g_pooledA[((size_t)b*NF + f)*Dm + tid], acc);
    }
    if (tid < 32){
        float v = pbm[tid] + pbm[tid+32] + pbm[tid+64] + pbm[tid+96];
        v += __shfl_xor_sync(0xffffffffu, v, 1);
        v += __shfl_xor_sync(0xffffffffu, v, 2);
        v += __shfl_xor_sync(0xffffffffu, v, 4);
        v += __shfl_xor_sync(0xffffffffu, v, 8);
        v += __shfl_xor_sync(0xffffffffu, v, 16);
        if (tid == 0) atomicAdd(&g_pooledB[b*NF + f], v);
    }
}

// ---------------------------------------------------------------------------
// K3 / Pass 2a: weight GRN split-K partials. grid = 256 (f*8 + slice), 256 thr.
// ---------------------------------------------------------------------------
__global__ void __launch_bounds__(256,1) vsn_pass2a(
    const float* __restrict__ lng,const float* __restrict__ lnb,
    const float* __restrict__ W1, const float* __restrict__ Ws)
{
    __shared__ float fp_s[32][16];
    __shared__ float pb_s[16];

    const int f = blockIdx.x >> 3, slice = blockIdx.x & 7;
    const int j0 = slice * 32;
    const int tid = threadIdx.x;
    const float invT = 1.f/(float)Tt;

    if (tid < 16) pb_s[tid] = g_pooledB[tid*NF + f];
    __syncthreads();

    {
        const int j = tid & 31, b8 = tid >> 5;
        const float lg = lng[f*Dm + j0 + j], lb = lnb[f*Dm + j0 + j];
        #pragma unroll
        for (int bb = 0; bb < 2; bb++){
            int b = b8*2 + bb;
            float pa = g_pooledA[((size_t)b*NF + f)*Dm + j0 + j];
            fp_s[j][b] = fmaf(lg*(pa - pb_s[b]), invT, lb);
        }
    }
    __syncthreads();

    {
        float acc[16];
        #pragma unroll
        for (int b = 0; b < 16; b++) acc[b] = 0.f;
        const float* w1p = W1 + (size_t)(f*256 + j0)*Dm + tid;
        #pragma unroll 4
        for (int j = 0; j < 32; j++){
            float w = w1p[(size_t)j*Dm];
            const float4* fv = (const float4*)fp_s[j];
            float4 f0 = fv[0], f1 = fv[1], f2 = fv[2], f3 = fv[3];
            acc[0]  = fmaf(f0.x, w, acc[0]);  acc[1]  = fmaf(f0.y, w, acc[1]);
            acc[2]  = fmaf(f0.z, w, acc[2]);  acc[3]  = fmaf(f0.w, w, acc[3]);
            acc[4]  = fmaf(f1.x, w, acc[4]);  acc[5]  = fmaf(f1.y, w, acc[5]);
            acc[6]  = fmaf(f1.z, w, acc[6]);  acc[7]  = fmaf(f1.w, w, acc[7]);
            acc[8]  = fmaf(f2.x, w, acc[8]);  acc[9]  = fmaf(f2.y, w, acc[9]);
            acc[10] = fmaf(f2.z, w, acc[10]); acc[11] = fmaf(f2.w, w, acc[11]);
            acc[12] = fmaf(f3.x, w, acc[12]); acc[13] = fmaf(f3.y, w, acc[13]);
            acc[14] = fmaf(f3.z, w, acc[14]); acc[15] = fmaf(f3.w, w, acc[15]);
        }
        #pragma unroll
        for (int b = 0; b < 16; b++)
            atomicAdd(&g_h1[b*Dm + tid], acc[b]);
    }

    {
        const int k = tid & 31, bg2 = tid >> 5;
        float a0 = 0.f, a1 = 0.f;
        const float* wsp = Ws + (size_t)(f*256 + j0)*NF + k;
        #pragma unroll 4
        for (int j = 0; j < 32; j++){
            float w = wsp[(size_t)j*NF];
            a0 = fmaf(fp_s[j][bg2],   w, a0);
            a1 = fmaf(fp_s[j][bg2+8], w, a1);
        }
        atomicAdd(&g_sk[bg2*NF + k], a0);
        atomicAdd(&g_sk[(bg2+8)*NF + k], a1);
    }
}

// ---------------------------------------------------------------------------
// K4 / Pass 2b: finalize weight GRN per batch. grid = 16, 256 threads.
// ---------------------------------------------------------------------------
__global__ void __launch_bounds__(256,1) vsn_pass2b(
    const float* __restrict__ B1,
    const float* __restrict__ W2, const float* __restrict__ B2,
    const float* __restrict__ Wg, const float* __restrict__ Bg,
    const float* __restrict__ Bs,
    const float* __restrict__ LNg,const float* __restrict__ LNb,
    float* wout)
{
    __shared__ float hw_s[Dm];
    __shared__ float part2[8][NF], part3[8][NF];
    const int b = blockIdx.x, tid = threadIdx.x;

    hw_s[tid] = eluf(g_h1[b*Dm + tid] + B1[tid]);
    __syncthreads();
    {
        const int k = tid & 31, pt = tid >> 5;
        float a2 = 0.f, a3 = 0.f;
        const int d0 = pt*32;
        #pragma unroll
        for (int d = d0; d < d0 + 32; d++){
            float h = hw_s[d];
            a2 = fmaf(h, W2[d*NF + k], a2);
            a3 = fmaf(h, Wg[d*NF + k], a3);
        }
        part2[pt][k] = a2; part3[pt][k] = a3;
    }
    __syncthreads();
    if (tid < 32){
        const int k = tid;
        float pw = B2[k], gw = Bg[k];
        #pragma unroll
        for (int p = 0; p < 8; p++){ pw += part2[p][k]; gw += part3[p][k]; }
        float sk = g_sk[b*NF + k] + Bs[k];
        float v = sk + sigf(gw) * pw;
        float s = v, ssq = v*v;
        #pragma unroll
        for (int o = 16; o > 0; o >>= 1){
            s   += __shfl_xor_sync(0xffffffffu, s, o);
            ssq += __shfl_xor_sync(0xffffffffu, ssq, o);
        }
        float mu = s * (1.f/32.f);
        float var = ssq * (1.f/32.f) - mu*mu;
        float y = fmaf((v - mu) * rsqrtf(var + 1e-5f), LNg[k], LNb[k]);
        float mx = y;
        #pragma unroll
        for (int o = 16; o > 0; o >>= 1) mx = fmaxf(mx, __shfl_xor_sync(0xffffffffu, mx, o));
        float e = expf(y - mx);
        float se = e;
        #pragma unroll
        for (int o = 16; o > 0; o >>= 1) se += __shfl_xor_sync(0xffffffffu, se, o);
        float w = e / se;
        g_weights[b*NF + k] = w;
        if (wout) wout[b*NF + k] = w;
    }
}

// ---------------------------------------------------------------------------
// K5 / Pass 3: fused LN + weighted combine (DRAM-roofline).
// ---------------------------------------------------------------------------
__global__ void __launch_bounds__(256,1) vsn_pass3(
    const float* __restrict__ lng, const float* __restrict__ lnb,
    float* __restrict__ out)
{
    __shared__ float A_s[8][NF], D_s[8][NF], w_s[NF];
    const int p0 = blockIdx.x * 8;
    const int b  = p0 >> 9;
    const int tid = threadIdx.x;

    if (tid < NF) w_s[tid] = g_weights[b*NF + tid];
    __syncthreads();
    {
        const int i = tid >> 5, f2 = tid & 31;
        float rsv = g_rs[(size_t)(p0 + i)*NF + f2];
        float muv = g_mu[(size_t)(p0 + i)*NF + f2];
        float a = w_s[f2] * rsv;
        A_s[i][f2] = a;
        D_s[i][f2] = a * muv;
    }
    float lngr[NF];
    float bias = 0.f;
    #pragma unroll
    for (int f2 = 0; f2 < NF; f2++){
        lngr[f2] = lng[f2*Dm + tid];
        bias = fmaf(lnb[f2*Dm + tid], w_s[f2], bias);
    }
    __syncthreads();

    #pragma unroll
    for (int i = 0; i < 8; i++){
        const float* yrow = g_stacked + ((size_t)(p0 + i)*NF)*Dm + tid;
        float acc = bias;
        #pragma unroll
        for (int f2 = 0; f2 < NF; f2++){
            float y = yrow[(size_t)f2*Dm];
            float t = fmaf(y, A_s[i][f2], -D_s[i][f2]);
            acc = fmaf(lngr[f2], t, acc);
        }
        out[(size_t)(p0 + i)*Dm + tid] = acc;
    }
}

// ---------------------------------------------------------------------------
extern "C" void kernel_launch(void* const* d_in, const int* in_sizes, int n_in,
                              void* d_out, int out_size)
{
    const float* x   = (const float*)d_in[0];
    const float* w1  = (const float*)d_in[1];
    const float* b1  = (const float*)d_in[2];
    const float* w2  = (const float*)d_in[3];
    const float* b2  = (const float*)d_in[4];
    const float* wg  = (const float*)d_in[5];
    const float* bg  = (const float*)d_in[6];
    const float* ws  = (const float*)d_in[7];
    const float* bs  = (const float*)d_in[8];
    const float* lng = (const float*)d_in[9];
    const float* lnb = (const float*)d_in[10];
    const float* W1  = (const float*)d_in[11];
    const float* B1  = (const float*)d_in[12];
    const float* W2  = (const float*)d_in[13];
    const float* B2  = (const float*)d_in[14];
    const float* Wg  = (const float*)d_in[15];
    const float* Bg  = (const float*)d_in[16];
    const float* Ws  = (const float*)d_in[17];
    const float* Bs  = (const float*)d_in[18];
    const float* LNg = (const float*)d_in[19];
    const float* LNb = (const float*)d_in[20];

    cudaFuncSetAttribute(vsn_pass1, cudaFuncAttributeMaxDynamicSharedMemorySize, SMEM1_BYTES);

    float* out = (float*)d_out;
    float* wout = (out_size > BT*Dm) ? out + (size_t)BT*Dm : nullptr;

    vsn_prep<<<514, 256>>>(w2, wg);
    dim3 g1(NF, BT/MT);
    vsn_pass1<<<g1, 256, SMEM1_BYTES>>>(x, w1, b1, b2, bg, ws, bs);
    vsn_pass2a<<<256, 256>>>(lng, lnb, W1, Ws);
    vsn_pass2b<<<16, 256>>>(B1, W2, B2, Wg, Bg, Bs, LNg, LNb, wout);
    vsn_pass3<<<1024, 256>>>(lng, lnb, out);
}

// round 17
// speedup vs baseline: 1.2001x; 1.1403x over previous
#include <cuda_runtime.h>
#include <cuda_fp16.h>
#include <math.h>
#include <stdint.h>

#define NF 32
#define Dm 256
#define Hh 128
#define Bb 16
#define Tt 512
#define BT (Bb*Tt)      // 8192 positions
#define MT 128          // positions per CTA in pass1
#define PW 136          // fp16 pitch (elems) of prepped weight / h tiles
#define PWB 272         // bytes

// ---------------- scratch (device globals; no runtime allocation) ----------
__device__ float g_stacked[(size_t)BT*NF*Dm];   // 268 MB pre-LN y (B,T,F,D)
__device__ float g_rs[(size_t)BT*NF];           // per (p,f) 1/std
__device__ float g_mu[(size_t)BT*NF];           // per (p,f) mean
__device__ float g_pooledA[Bb*NF*Dm];           // sum_t rs_t * y[t,d]
__device__ float g_pooledB[Bb*NF];              // sum_t rs_t * mu_t
__device__ float g_weights[Bb*NF];
__device__ float g_h1[Bb*Dm];                   // split-K partials of fp@W1
__device__ float g_sk[Bb*NF];                   // split-K partials of fp@Ws
// prepped weights: 128 parts (f*4 + t*2 + hilo), each [256 d][136 k] fp16
__device__ uint4 g_wprep4[128 * 4352];          // 8.9 MB

// ---------------- helpers --------------------------------------------------
__device__ __forceinline__ uint32_t smem_u32(const void* p){
    uint32_t a;
    asm("{ .reg .u64 t; cvta.to.shared.u64 t, %1; cvt.u32.u64 %0, t; }" : "=r"(a) : "l"(p));
    return a;
}
__device__ __forceinline__ void ldsm_x4(uint32_t (&r)[4], uint32_t a){
    asm volatile("ldmatrix.sync.aligned.m8n8.x4.shared.b16 {%0,%1,%2,%3}, [%4];"
        : "=r"(r[0]),"=r"(r[1]),"=r"(r[2]),"=r"(r[3]) : "r"(a));
}
__device__ __forceinline__ void ldsm_x2(uint32_t (&r)[2], uint32_t a){
    asm volatile("ldmatrix.sync.aligned.m8n8.x2.shared.b16 {%0,%1}, [%2];"
        : "=r"(r[0]),"=r"(r[1]) : "r"(a));
}
__device__ __forceinline__ void mma16816h(float* c, const uint32_t (&a)[4], const uint32_t (&b)[2]){
    asm volatile("mma.sync.aligned.m16n8k16.row.col.f32.f16.f16.f32 "
        "{%0,%1,%2,%3}, {%4,%5,%6,%7}, {%8,%9}, {%0,%1,%2,%3};"
        : "+f"(c[0]),"+f"(c[1]),"+f"(c[2]),"+f"(c[3])
        : "r"(a[0]),"r"(a[1]),"r"(a[2]),"r"(a[3]), "r"(b[0]),"r"(b[1]));
}
#define CP16(d,s)    asm volatile("cp.async.cg.shared.global [%0], [%1], 16;" :: "r"(d), "l"(s) : "memory")
#define CP_COMMIT()  asm volatile("cp.async.commit_group;" ::: "memory")
#define CP_WAIT(n)   asm volatile("cp.async.wait_group %0;" :: "n"(n) : "memory")

__device__ __forceinline__ float eluf(float z){ return z > 0.f ? z : expm1f(z); }
__device__ __forceinline__ float sigf(float z){ return __fdividef(1.f, 1.f + __expf(-z)); }

// ---------------------------------------------------------------------------
// K1: prep (w2/wg -> fp16 hi/lo transposed pitch-136 images) + zero scratch.
// grid = 514: blocks 0..511 prep (f,t,p,dc), 512..513 zero.
// ---------------------------------------------------------------------------
__global__ void __launch_bounds__(256,1) vsn_prep(const float* __restrict__ w2,
                                                  const float* __restrict__ wg)
{
    __shared__ float ts[128][65];
    const int bid = blockIdx.x;
    const int tid = threadIdx.x;

    if (bid >= 512){
        int z = bid - 512;
        for (int i = z*65536 + tid; i < z*65536 + 65536; i += 256) g_pooledA[i] = 0.f;
        if (z == 0){
            for (int i = tid; i < Bb*Dm; i += 256) g_h1[i] = 0.f;
            for (int i = tid; i < Bb*NF; i += 256){ g_sk[i] = 0.f; g_pooledB[i] = 0.f; }
        }
        return;
    }

    const int f = bid >> 4, t = (bid >> 3) & 1, p = (bid >> 2) & 1, dc = bid & 3;
    const int part = (f*2 + t)*2 + p;
    const float* W = (t ? wg : w2) + (size_t)f*Hh*Dm;             // [k][d]
    __half* dst = (__half*)(g_wprep4 + (size_t)part*4352);        // [d][k pitch 136]

    #pragma unroll
    for (int i = 0; i < 32; i++){
        int e = tid + i*256;
        int d = e & 63, k = e >> 6;
        ts[k][d] = W[(size_t)k*Dm + dc*64 + d];
    }
    __syncthreads();
    #pragma unroll
    for (int i = 0; i < 4; i++){
        int g = tid + i*256;
        int d = g >> 4, kg = g & 15;
        union { __half h[8]; uint4 v; } o;
        #pragma unroll
        for (int j = 0; j < 8; j++){
            float v = ts[kg*8 + j][d];
            __half hi = __float2half_rn(v);
            o.h[j] = p ? __float2half_rn(v - __half2float(hi)) : hi;
        }
        *(uint4*)(dst + (size_t)(dc*64 + d)*PW + kg*8) = o.v;
    }
}

// ---------------------------------------------------------------------------
// K2 / Pass 1: HMMA fp16, MT=128, DC=32, 2 CTAs/SM.
// R17: h single fp16 tile (no A-lo); proj = h*(w2hi + w2lo) [w split],
// gate = h*wg_hi. 3 MMA/group. Ping-pong double-buffered weights, 1 sync/chunk.
// grid = (NF, 64), 256 threads, 92672 B dyn smem.
// ---------------------------------------------------------------------------
#define OFF_HH  0               // 34816 = [128][272 B] fp16 h
#define OFF_WT  34816           // 2 bufs x (3 parts x 8704) = 52224
#define OFF_B2  87040
#define OFF_BG  88064
#define OFF_WS  89088
#define OFF_BS  90112
#define OFF_W1  91136
#define OFF_B1  91648
#define OFF_X   92160
#define SMEM1_BYTES 92672
// post-loop overlays in WT: sred [2][128]f32 @+0, ssq @+1024, rs_s[128] @+2048,
// pbm[128] @+2560

extern __shared__ char sm1[];

__global__ void __launch_bounds__(256,2) vsn_pass1(
    const float* __restrict__ x,  const float* __restrict__ w1, const float* __restrict__ b1,
    const float* __restrict__ b2, const float* __restrict__ bg,
    const float* __restrict__ ws, const float* __restrict__ bs)
{
    const int f     = blockIdx.x;
    const int pbase = blockIdx.y * MT;
    const int b     = pbase >> 9;
    const int tid   = threadIdx.x;
    const int lane  = tid & 31;
    const int wid   = tid >> 5;
    const int q     = wid & 1;      // 16-col group within 32-d chunk
    const int rg    = wid >> 1;     // 32-row group

    char* HH  = sm1 + OFF_HH;
    float* b2_s = (float*)(sm1 + OFF_B2);
    float* bg_s = (float*)(sm1 + OFF_BG);
    float* ws_s = (float*)(sm1 + OFF_WS);
    float* bs_s = (float*)(sm1 + OFF_BS);
    float* w1_s = (float*)(sm1 + OFF_W1);
    float* b1_s = (float*)(sm1 + OFF_B1);
    float* x_s  = (float*)(sm1 + OFF_X);

    const uint32_t sb  = smem_u32(sm1);
    const uint32_t aHH = sb + OFF_HH, wtb = sb + OFF_WT;
    const char* wsrc = (const char*)g_wprep4 + (size_t)f*4*69632;

    // stage parts into buffer (c&1): 0 = w2_hi, 1 = w2_lo, 2 = wg_hi
    auto stage = [&](int c){
        const char* srcc = wsrc + (size_t)c*8704;
        const uint32_t dstb = wtb + (uint32_t)((c & 1)*26112);
        #pragma unroll
        for (int p4 = 0; p4 < 3; p4++){
            const char* src = srcc + (size_t)p4*69632;
            const uint32_t dst = dstb + p4*8704;
            CP16(dst + tid*16,       src + (size_t)tid*16);
            CP16(dst + (256+tid)*16, src + (size_t)(256+tid)*16);
            if (tid < 32) CP16(dst + (512+tid)*16, src + (size_t)(512+tid)*16);
        }
    };

    stage(0); CP_COMMIT();

    // ---- stage params ----
    b2_s[tid] = b2[f*Dm + tid];
    bg_s[tid] = bg[f*Dm + tid];
    ws_s[tid] = ws[f*Dm + tid];
    bs_s[tid] = bs[f*Dm + tid];
    if (tid < 128){ w1_s[tid] = w1[f*Hh + tid]; b1_s[tid] = b1[f*Hh + tid]; }
    if (tid < 128) x_s[tid] = x[(size_t)(pbase + tid)*NF + f];
    __syncthreads();

    // ---- h as single fp16 tile (row r = tid>>1, k-half (tid&1)*64) ----
    {
        const int r = tid >> 1, k0 = (tid & 1)*64;
        const float x_r = x_s[r];
        #pragma unroll
        for (int j = 0; j < 64; j += 2){
            float v0 = eluf(fmaf(x_r, w1_s[k0+j],   b1_s[k0+j]));
            float v1 = eluf(fmaf(x_r, w1_s[k0+j+1], b1_s[k0+j+1]));
            union { __half h[2]; uint32_t u; } hv;
            hv.h[0] = __float2half_rn(v0);
            hv.h[1] = __float2half_rn(v1);
            *(uint32_t*)(HH + r*PWB + (k0+j)*2) = hv.u;
        }
    }

    const uint32_t a_off = (uint32_t)(((lane & 7) + 8*((lane>>3)&1)) * PWB + ((lane>>4)&1)*16);
    const uint32_t b_off = (uint32_t)((q*16 + (lane & 7)) * PWB + ((lane>>3)&1)*16);

    float srow[4], ssqrow[4];
    #pragma unroll
    for (int i = 0; i < 4; i++){ srow[i] = 0.f; ssqrow[i] = 0.f; }

    for (int c = 0; c < 8; c++){
        CP_WAIT(0);
        __syncthreads();   // buffer (c&1) ready; all warps done with buffer ((c+1)&1)
                           // reads from chunk c-1; orders h/param writes on c=0
        if (c + 1 < 8){ stage(c + 1); CP_COMMIT(); }   // lands during MMA+epilogue

        const uint32_t wb = wtb + (uint32_t)((c & 1)*26112);
        float accp[2][2][4], accg[2][2][4];
        #pragma unroll
        for (int i = 0; i < 2; i++)
            #pragma unroll
            for (int j = 0; j < 2; j++)
                #pragma unroll
                for (int k2 = 0; k2 < 4; k2++){ accp[i][j][k2] = 0.f; accg[i][j][k2] = 0.f; }

        #pragma unroll 2
        for (int kk = 0; kk < 8; kk++){
            uint32_t Bph[2][2], Bpl[2][2], Bgh[2][2];
            #pragma unroll
            for (int nt = 0; nt < 2; nt++){
                const uint32_t bb = b_off + (uint32_t)(nt*(8*PWB)) + kk*32;
                ldsm_x2(Bph[nt], wb + bb);
                ldsm_x2(Bpl[nt], wb + 8704  + bb);
                ldsm_x2(Bgh[nt], wb + 17408 + bb);
            }
            #pragma unroll
            for (int mt = 0; mt < 2; mt++){
                uint32_t Ah[4];
                const uint32_t aa = (uint32_t)((rg*32 + mt*16)*PWB) + a_off + kk*32;
                ldsm_x4(Ah, aHH + aa);
                #pragma unroll
                for (int nt = 0; nt < 2; nt++){
                    mma16816h(accp[mt][nt], Ah, Bph[nt]);   // proj h*w_hi
                    mma16816h(accp[mt][nt], Ah, Bpl[nt]);   // proj h*w_lo
                    mma16816h(accg[mt][nt], Ah, Bgh[nt]);   // gate h*wg
                }
            }
        }

        // ---- epilogue: y pre-LN -> gmem, running stats ----
        #pragma unroll
        for (int mt = 0; mt < 2; mt++)
            #pragma unroll
            for (int hf = 0; hf < 2; hf++){
                const int m = rg*32 + mt*16 + (lane>>2) + 8*hf;
                const float xm = x_s[m];
                float* yrow = g_stacked + ((size_t)(pbase + m)*NF + f)*Dm;
                float sacc = 0.f, qacc = 0.f;
                #pragma unroll
                for (int nt = 0; nt < 2; nt++){
                    const int dg = c*32 + q*16 + nt*8 + (lane & 3)*2;
                    float p0 = accp[mt][nt][hf*2+0] + b2_s[dg];
                    float p1 = accp[mt][nt][hf*2+1] + b2_s[dg+1];
                    float g0 = sigf(accg[mt][nt][hf*2+0] + bg_s[dg]);
                    float g1 = sigf(accg[mt][nt][hf*2+1] + bg_s[dg+1]);
                    float y0 = fmaf(xm, ws_s[dg],   bs_s[dg])   + g0*p0;
                    float y1 = fmaf(xm, ws_s[dg+1], bs_s[dg+1]) + g1*p1;
                    float2 yy; yy.x = y0; yy.y = y1;
                    *(float2*)(yrow + dg) = yy;
                    sacc += y0 + y1;
                    qacc = fmaf(y0, y0, fmaf(y1, y1, qacc));
                }
                srow[mt*2 + hf] += sacc;
                ssqrow[mt*2 + hf] += qacc;
            }
    }

    // ---- LN stats -> g_rs / g_mu ----
    __syncthreads();
    float* sred   = (float*)(sm1 + OFF_WT);         // [2 q][128 m]
    float* ssqred = sred + 256;
    float* rs_s   = (float*)(sm1 + OFF_WT + 2048);  // [128]
    float* pbm    = (float*)(sm1 + OFF_WT + 2560);  // [128]
    #pragma unroll
    for (int i = 0; i < 4; i++){
        float v = srow[i], w2v = ssqrow[i];
        v += __shfl_xor_sync(0xffffffffu, v, 1);  w2v += __shfl_xor_sync(0xffffffffu, w2v, 1);
        v += __shfl_xor_sync(0xffffffffu, v, 2);  w2v += __shfl_xor_sync(0xffffffffu, w2v, 2);
        if ((lane & 3) == 0){
            const int m = rg*32 + (i>>1)*16 + (lane>>2) + 8*(i & 1);
            sred[q*128 + m]   = v;
            ssqred[q*128 + m] = w2v;
        }
    }
    __syncthreads();
    if (tid < 128){
        float s  = sred[tid] + sred[128+tid];
        float sq = ssqred[tid] + ssqred[128+tid];
        float mu = s * (1.f/256.f);
        float var = sq * (1.f/256.f) - mu*mu;
        float rs = rsqrtf(var + 1e-5f);
        g_rs[(size_t)(pbase + tid)*NF + f] = rs;
        g_mu[(size_t)(pbase + tid)*NF + f] = mu;
        rs_s[tid] = rs;
        pbm[tid]  = rs * mu;
    }
    __syncthreads();

    // ---- fused pool: L2-hot readback of this CTA's y, 1 atomic per d ----
    {
        const float* yp = g_stacked + ((size_t)pbase*NF + f)*Dm + tid;
        float acc = 0.f;
        #pragma unroll 8
        for (int m = 0; m < 128; m++)
            acc = fmaf(rs_s[m], yp[(size_t)m*NF*Dm], acc);
        atomicAdd(&g_pooledA[((size_t)b*NF + f)*Dm + tid], acc);
    }
    if (tid < 32){
        float v = pbm[tid] + pbm[tid+32] + pbm[tid+64] + pbm[tid+96];
        v += __shfl_xor_sync(0xffffffffu, v, 1);
        v += __shfl_xor_sync(0xffffffffu, v, 2);
        v += __shfl_xor_sync(0xffffffffu, v, 4);
        v += __shfl_xor_sync(0xffffffffu, v, 8);
        v += __shfl_xor_sync(0xffffffffu, v, 16);
        if (tid == 0) atomicAdd(&g_pooledB[b*NF + f], v);
    }
}

// ---------------------------------------------------------------------------
// K3 / Pass 2a: weight GRN split-K partials. grid = 256 (f*8 + slice), 256 thr.
// ---------------------------------------------------------------------------
__global__ void __launch_bounds__(256,1) vsn_pass2a(
    const float* __restrict__ lng,const float* __restrict__ lnb,
    const float* __restrict__ W1, const float* __restrict__ Ws)
{
    __shared__ float fp_s[32][16];
    __shared__ float pb_s[16];

    const int f = blockIdx.x >> 3, slice = blockIdx.x & 7;
    const int j0 = slice * 32;
    const int tid = threadIdx.x;
    const float invT = 1.f/(float)Tt;

    if (tid < 16) pb_s[tid] = g_pooledB[tid*NF + f];
    __syncthreads();

    {
        const int j = tid & 31, b8 = tid >> 5;
        const float lg = lng[f*Dm + j0 + j], lb = lnb[f*Dm + j0 + j];
        #pragma unroll
        for (int bb = 0; bb < 2; bb++){
            int b = b8*2 + bb;
            float pa = g_pooledA[((size_t)b*NF + f)*Dm + j0 + j];
            fp_s[j][b] = fmaf(lg*(pa - pb_s[b]), invT, lb);
        }
    }
    __syncthreads();

    {
        float acc[16];
        #pragma unroll
        for (int b = 0; b < 16; b++) acc[b] = 0.f;
        const float* w1p = W1 + (size_t)(f*256 + j0)*Dm + tid;
        #pragma unroll 4
        for (int j = 0; j < 32; j++){
            float w = w1p[(size_t)j*Dm];
            const float4* fv = (const float4*)fp_s[j];
            float4 f0 = fv[0], f1 = fv[1], f2 = fv[2], f3 = fv[3];
            acc[0]  = fmaf(f0.x, w, acc[0]);  acc[1]  = fmaf(f0.y, w, acc[1]);
            acc[2]  = fmaf(f0.z, w, acc[2]);  acc[3]  = fmaf(f0.w, w, acc[3]);
            acc[4]  = fmaf(f1.x, w, acc[4]);  acc[5]  = fmaf(f1.y, w, acc[5]);
            acc[6]  = fmaf(f1.z, w, acc[6]);  acc[7]  = fmaf(f1.w, w, acc[7]);
            acc[8]  = fmaf(f2.x, w, acc[8]);  acc[9]  = fmaf(f2.y, w, acc[9]);
            acc[10] = fmaf(f2.z, w, acc[10]); acc[11] = fmaf(f2.w, w, acc[11]);
            acc[12] = fmaf(f3.x, w, acc[12]); acc[13] = fmaf(f3.y, w, acc[13]);
            acc[14] = fmaf(f3.z, w, acc[14]); acc[15] = fmaf(f3.w, w, acc[15]);
        }
        #pragma unroll
        for (int b = 0; b < 16; b++)
            atomicAdd(&g_h1[b*Dm + tid], acc[b]);
    }

    {
        const int k = tid & 31, bg2 = tid >> 5;
        float a0 = 0.f, a1 = 0.f;
        const float* wsp = Ws + (size_t)(f*256 + j0)*NF + k;
        #pragma unroll 4
        for (int j = 0; j < 32; j++){
            float w = wsp[(size_t)j*NF];
            a0 = fmaf(fp_s[j][bg2],   w, a0);
            a1 = fmaf(fp_s[j][bg2+8], w, a1);
        }
        atomicAdd(&g_sk[bg2*NF + k], a0);
        atomicAdd(&g_sk[(bg2+8)*NF + k], a1);
    }
}

// ---------------------------------------------------------------------------
// K4 / Pass 2b: finalize weight GRN per batch. grid = 16, 256 threads.
// ---------------------------------------------------------------------------
__global__ void __launch_bounds__(256,1) vsn_pass2b(
    const float* __restrict__ B1,
    const float* __restrict__ W2, const float* __restrict__ B2,
    const float* __restrict__ Wg, const float* __restrict__ Bg,
    const float* __restrict__ Bs,
    const float* __restrict__ LNg,const float* __restrict__ LNb,
    float* wout)
{
    __shared__ float hw_s[Dm];
    __shared__ float part2[8][NF], part3[8][NF];
    const int b = blockIdx.x, tid = threadIdx.x;

    hw_s[tid] = eluf(g_h1[b*Dm + tid] + B1[tid]);
    __syncthreads();
    {
        const int k = tid & 31, pt = tid >> 5;
        float a2 = 0.f, a3 = 0.f;
        const int d0 = pt*32;
        #pragma unroll
        for (int d = d0; d < d0 + 32; d++){
            float h = hw_s[d];
            a2 = fmaf(h, W2[d*NF + k], a2);
            a3 = fmaf(h, Wg[d*NF + k], a3);
        }
        part2[pt][k] = a2; part3[pt][k] = a3;
    }
    __syncthreads();
    if (tid < 32){
        const int k = tid;
        float pw = B2[k], gw = Bg[k];
        #pragma unroll
        for (int p = 0; p < 8; p++){ pw += part2[p][k]; gw += part3[p][k]; }
        float sk = g_sk[b*NF + k] + Bs[k];
        float v = sk + sigf(gw) * pw;
        float s = v, ssq = v*v;
        #pragma unroll
        for (int o = 16; o > 0; o >>= 1){
            s   += __shfl_xor_sync(0xffffffffu, s, o);
            ssq += __shfl_xor_sync(0xffffffffu, ssq, o);
        }
        float mu = s * (1.f/32.f);
        float var = ssq * (1.f/32.f) - mu*mu;
        float y = fmaf((v - mu) * rsqrtf(var + 1e-5f), LNg[k], LNb[k]);
        float mx = y;
        #pragma unroll
        for (int o = 16; o > 0; o >>= 1) mx = fmaxf(mx, __shfl_xor_sync(0xffffffffu, mx, o));
        float e = expf(y - mx);
        float se = e;
        #pragma unroll
        for (int o = 16; o > 0; o >>= 1) se += __shfl_xor_sync(0xffffffffu, se, o);
        float w = e / se;
        g_weights[b*NF + k] = w;
        if (wout) wout[b*NF + k] = w;
    }
}

// ---------------------------------------------------------------------------
// K5 / Pass 3: fused LN + weighted combine (DRAM-roofline).
// ---------------------------------------------------------------------------
__global__ void __launch_bounds__(256,1) vsn_pass3(
    const float* __restrict__ lng, const float* __restrict__ lnb,
    float* __restrict__ out)
{
    __shared__ float A_s[8][NF], D_s[8][NF], w_s[NF];
    const int p0 = blockIdx.x * 8;
    const int b  = p0 >> 9;
    const int tid = threadIdx.x;

    if (tid < NF) w_s[tid] = g_weights[b*NF + tid];
    __syncthreads();
    {
        const int i = tid >> 5, f2 = tid & 31;
        float rsv = g_rs[(size_t)(p0 + i)*NF + f2];
        float muv = g_mu[(size_t)(p0 + i)*NF + f2];
        float a = w_s[f2] * rsv;
        A_s[i][f2] = a;
        D_s[i][f2] = a * muv;
    }
    float lngr[NF];
    float bias = 0.f;
    #pragma unroll
    for (int f2 = 0; f2 < NF; f2++){
        lngr[f2] = lng[f2*Dm + tid];
        bias = fmaf(lnb[f2*Dm + tid], w_s[f2], bias);
    }
    __syncthreads();

    #pragma unroll
    for (int i = 0; i < 8; i++){
        const float* yrow = g_stacked + ((size_t)(p0 + i)*NF)*Dm + tid;
        float acc = bias;
        #pragma unroll
        for (int f2 = 0; f2 < NF; f2++){
            float y = yrow[(size_t)f2*Dm];
            float t = fmaf(y, A_s[i][f2], -D_s[i][f2]);
            acc = fmaf(lngr[f2], t, acc);
        }
        out[(size_t)(p0 + i)*Dm + tid] = acc;
    }
}

// ---------------------------------------------------------------------------
extern "C" void kernel_launch(void* const* d_in, const int* in_sizes, int n_in,
                              void* d_out, int out_size)
{
    const float* x   = (const float*)d_in[0];
    const float* w1  = (const float*)d_in[1];
    const float* b1  = (const float*)d_in[2];
    const float* w2  = (const float*)d_in[3];
    const float* b2  = (const float*)d_in[4];
    const float* wg  = (const float*)d_in[5];
    const float* bg  = (const float*)d_in[6];
    const float* ws  = (const float*)d_in[7];
    const float* bs  = (const float*)d_in[8];
    const float* lng = (const float*)d_in[9];
    const float* lnb = (const float*)d_in[10];
    const float* W1  = (const float*)d_in[11];
    const float* B1  = (const float*)d_in[12];
    const float* W2  = (const float*)d_in[13];
    const float* B2  = (const float*)d_in[14];
    const float* Wg  = (const float*)d_in[15];
    const float* Bg  = (const float*)d_in[16];
    const float* Ws  = (const float*)d_in[17];
    const float* Bs  = (const float*)d_in[18];
    const float* LNg = (const float*)d_in[19];
    const float* LNb = (const float*)d_in[20];

    cudaFuncSetAttribute(vsn_pass1, cudaFuncAttributeMaxDynamicSharedMemorySize, SMEM1_BYTES);

    float* out = (float*)d_out;
    float* wout = (out_size > BT*Dm) ? out + (size_t)BT*Dm : nullptr;

    vsn_prep<<<514, 256>>>(w2, wg);
    dim3 g1(NF, BT/MT);
    vsn_pass1<<<g1, 256, SMEM1_BYTES>>>(x, w1, b1, b2, bg, ws, bs);
    vsn_pass2a<<<256, 256>>>(lng, lnb, W1, Ws);
    vsn_pass2b<<<16, 256>>>(B1, W2, B2, Wg, Bg, Bs, LNg, LNb, wout);
    vsn_pass3<<<1024, 256>>>(lng, lnb, out);
}